// round 9
// baseline (speedup 1.0000x reference)
#include <cuda_runtime.h>

#define BB 32
#define NN 2000
#define DD 5
#define GRP 5
#define TOPK 110
#define TPB 256
#define NCHUNK 16
#define CHUNK 128          // n's per block; 2 threads cooperate per n

typedef unsigned long long u64;

__device__ float g_diag[BB * NN];
__device__ unsigned int g_cnt[BB];   // monotonic; each launch adds exactly NCHUNK per batch

// ---- PTX helpers ----------------------------------------------------------
__device__ __forceinline__ float ex2(float x) {
    float y; asm("ex2.approx.ftz.f32 %0, %1;" : "=f"(y) : "f"(x)); return y;
}
__device__ __forceinline__ u64 pk(float lo, float hi) {
    u64 r; asm("mov.b64 %0, {%1, %2};" : "=l"(r) : "f"(lo), "f"(hi)); return r;
}
__device__ __forceinline__ float2 up(u64 v) {
    float2 r; asm("mov.b64 {%0, %1}, %2;" : "=f"(r.x), "=f"(r.y) : "l"(v)); return r;
}
__device__ __forceinline__ u64 fma2(u64 a, u64 b, u64 c) {
    u64 d; asm("fma.rn.f32x2 %0, %1, %2, %3;" : "=l"(d) : "l"(a), "l"(b), "l"(c)); return d;
}

// ---------------------------------------------------------------------------
// Fused kernel. grid = (16, 32), block = 256, 3 blocks/SM.
// score(n,m)*log2e = alpha_n . in[m] + const_n  (const cancels in softmax),
// alpha_n = (log2e/sqrt(5)) * Wi (Wk q_n)  -- 3-dim.
// Two threads per n: t and t+128 each sum one half of the m-range (fp32 ex2),
// combined through smem.
//
// smem sbuf (34048 B):
//   diag phase : P0 f32[2000] @0, P1 @8000, P2 @16000  (transposed in_mat[b])
//   select phase (overlay, last-arriving block only):
//     key u64[2000] @0, hist int[512] @16000, cand u64[2000] @18048
// ---------------------------------------------------------------------------
__global__ void __launch_bounds__(TPB, 3) fused_kernel(
    const float* __restrict__ in_mat,
    const float* __restrict__ Wi, const float* __restrict__ bi,
    const float* __restrict__ Wq, const float* __restrict__ bq,
    const float* __restrict__ Wk,
    float* __restrict__ out)
{
    __shared__ __align__(16) char sbuf[34048];
    __shared__ float wsm[75];   // 0:Wi(15) 15:bi(5) 20:Wq(25) 45:bq(5) 50:Wk(25)
    __shared__ float partial[TPB];
    __shared__ float redf[8];
    __shared__ float redf2[8];
    __shared__ int   redi[8];
    __shared__ float cen[3];
    __shared__ int s_ncand, s_bstar, s_last;
    __shared__ float s_dmin, s_dmax;

    const int b = blockIdx.y, c = blockIdx.x, t = threadIdx.x;
    const float* base_in = in_mat + b * NN * 3;

    float* P0 = (float*)(sbuf);
    float* P1 = (float*)(sbuf + 8000);
    float* P2 = (float*)(sbuf + 16000);

    // ---- stage weights ----
    if (t < 15)      wsm[t] = Wi[t];
    else if (t < 20) wsm[t] = bi[t - 15];
    else if (t < 45) wsm[t] = Wq[t - 20];
    else if (t < 50) wsm[t] = bq[t - 45];
    else if (t < 75) wsm[t] = Wk[t - 50];
    __syncthreads();

    // ---- phase 1: transpose in_mat[b] -> SoA smem, track max ||in||^2 ----
    float bmax = 0.0f;
    for (int p = t; p < NN; p += TPB) {
        float i0 = base_in[p * 3], i1 = base_in[p * 3 + 1], i2 = base_in[p * 3 + 2];
        P0[p] = i0; P1[p] = i1; P2[p] = i2;
        bmax = fmaxf(bmax, fmaf(i0, i0, fmaf(i1, i1, i2 * i2)));
    }
#pragma unroll
    for (int o = 16; o; o >>= 1) bmax = fmaxf(bmax, __shfl_xor_sync(0xffffffffu, bmax, o));
    if ((t & 31) == 0) redf[t >> 5] = bmax;
    __syncthreads();
    float maxn2 = redf[0];
#pragma unroll
    for (int i = 1; i < 8; i++) maxn2 = fmaxf(maxn2, redf[i]);

    // ---- phase 2: alpha_n; each thread sums half of the m-range ----
    const int tn = t & (CHUNK - 1);           // n-lane 0..127
    const int half = t >> 7;                  // 0: m in [0,1000), 1: [1000,2000)
    const int n = c * CHUNK + tn;
    const int nc_ = (n < NN) ? n : NN - 1;    // clamped for safe addressing

    float i0 = base_in[nc_ * 3], i1 = base_in[nc_ * 3 + 1], i2 = base_in[nc_ * 3 + 2];
    float a0, a1, a2, shift;
    {
        float x[DD];
#pragma unroll
        for (int j = 0; j < DD; j++)
            x[j] = fmaf(i0, wsm[j], fmaf(i1, wsm[5 + j], fmaf(i2, wsm[10 + j], wsm[15 + j])));
        float q[DD];
#pragma unroll
        for (int j = 0; j < DD; j++) {
            float qq = wsm[45 + j];
#pragma unroll
            for (int d = 0; d < DD; d++) qq = fmaf(x[d], wsm[20 + d * 5 + j], qq);
            q[j] = qq;
        }
        float wkq[DD];
#pragma unroll
        for (int d = 0; d < DD; d++) {
            float s = 0.f;
#pragma unroll
            for (int j = 0; j < DD; j++) s = fmaf(wsm[50 + d * 5 + j], q[j], s);
            wkq[d] = s;
        }
        const float qscale = 1.4426950408889634f / 2.2360679774997896f; // log2e/sqrt(5)
        a0 = 0.f; a1 = 0.f; a2 = 0.f;
#pragma unroll
        for (int d = 0; d < DD; d++) {
            a0 = fmaf(wsm[0 + d], wkq[d], a0);
            a1 = fmaf(wsm[5 + d], wkq[d], a1);
            a2 = fmaf(wsm[10 + d], wkq[d], a2);
        }
        a0 *= qscale; a1 *= qscale; a2 *= qscale;
        // shift >= max_m alpha . in[m] (Cauchy-Schwarz); softmax shift-invariant.
        shift = sqrtf(fmaf(a0, a0, fmaf(a1, a1, a2 * a2))) * sqrtf(maxn2);
    }

    {
        u64 ax = pk(a0, a0), ay = pk(a1, a1), az = pk(a2, a2);
        u64 ns = pk(-shift, -shift);

        const ulonglong2* Q0 = (const ulonglong2*)P0;
        const ulonglong2* Q1 = (const ulonglong2*)P1;
        const ulonglong2* Q2 = (const ulonglong2*)P2;

        const int pbeg = half * (NN / 8);     // 0 or 250 (ulonglong2 groups of 4 pts)
        const int pend = pbeg + (NN / 8);
        float sA = 0.f, sB = 0.f, sC = 0.f, sD = 0.f;
#pragma unroll 5
        for (int p = pbeg; p < pend; p++) {
            ulonglong2 A0 = Q0[p], A1 = Q1[p], A2 = Q2[p];
            u64 v0 = fma2(ax, A0.x, ns);
            v0 = fma2(ay, A1.x, v0);
            v0 = fma2(az, A2.x, v0);
            u64 v1 = fma2(ax, A0.y, ns);
            v1 = fma2(ay, A1.y, v1);
            v1 = fma2(az, A2.y, v1);
            float2 f0 = up(v0), f1 = up(v1);
            sA += ex2(f0.x);
            sB += ex2(f0.y);
            sC += ex2(f1.x);
            sD += ex2(f1.y);
        }
        partial[t] = (sA + sB) + (sC + sD);
    }
    __syncthreads();

    if (half == 0 && n < NN) {
        float zsum = partial[t] + partial[t + CHUNK];
        float vn = fmaf(a0, i0, fmaf(a1, i1, a2 * i2)) - shift;
        g_diag[b * NN + n] = ex2(vn) / zsum;
    }

    // ---- arrival: last block of batch b runs selection ----
    __threadfence();
    __syncthreads();
    if (t == 0) {
        unsigned old = atomicAdd(&g_cnt[b], 1u);
        s_last = ((old % NCHUNK) == NCHUNK - 1) ? 1 : 0;
    }
    __syncthreads();
    if (!s_last) return;
    __threadfence();

    // ================= selection (one block per batch) ====================
    const float* db = g_diag + b * NN;

    // group sums + argmax (first-max tie-break == jnp.argmax)
    {
        float bv = -1e30f; int gi = 1 << 30;
        for (int g = t; g < NN / GRP; g += TPB) {
            const float* d5 = db + g * GRP;
            float s = d5[0] + d5[1] + d5[2] + d5[3] + d5[4];
            if (s > bv) { bv = s; gi = g; }
        }
#pragma unroll
        for (int o = 16; o; o >>= 1) {
            float ov = __shfl_xor_sync(0xffffffffu, bv, o);
            int   oi = __shfl_xor_sync(0xffffffffu, gi, o);
            if (ov > bv || (ov == bv && oi < gi)) { bv = ov; gi = oi; }
        }
        if ((t & 31) == 0) { redf[t >> 5] = bv; redi[t >> 5] = gi; }
        __syncthreads();
        if (t == 0) {
            float v = redf[0]; int gi2 = redi[0];
#pragma unroll
            for (int i = 1; i < 8; i++)
                if (redf[i] > v || (redf[i] == v && redi[i] < gi2)) { v = redf[i]; gi2 = redi[i]; }
            const float* gp = base_in + gi2 * GRP * 3;
            float cx = 0.f, cy = 0.f, cz = 0.f;
#pragma unroll
            for (int p = 0; p < GRP; p++) {
                cx += gp[p * 3 + 0]; cy += gp[p * 3 + 1]; cz += gp[p * 3 + 2];
            }
            cen[0] = cx * 0.2f; cen[1] = cy * 0.2f; cen[2] = cz * 0.2f;
        }
        __syncthreads();
    }

    u64* key  = (u64*)sbuf;
    int* hist = (int*)(sbuf + 16000);
    u64* cand = (u64*)(sbuf + 18048);

    // distances -> keys, min/max reduction
    {
        float cx = cen[0], cy = cen[1], cz = cen[2];
        float dmin = 1e30f, dmax = 0.0f;
        for (int m = t; m < NN; m += TPB) {
            const float* p = base_in + m * 3;
            float dx = p[0] - cx, dy = p[1] - cy, dz = p[2] - cz;
            float d = sqrtf(fmaf(dx, dx, fmaf(dy, dy, dz * dz)));
            key[m] = (((u64)__float_as_uint(d)) << 11) | (unsigned)m;
            dmin = fminf(dmin, d); dmax = fmaxf(dmax, d);
        }
#pragma unroll
        for (int o = 16; o; o >>= 1) {
            dmin = fminf(dmin, __shfl_xor_sync(0xffffffffu, dmin, o));
            dmax = fmaxf(dmax, __shfl_xor_sync(0xffffffffu, dmax, o));
        }
        if ((t & 31) == 0) { redf[t >> 5] = dmin; redf2[t >> 5] = dmax; }
        __syncthreads();
        if (t == 0) {
            float mn = redf[0], mx = redf2[0];
#pragma unroll
            for (int i = 1; i < 8; i++) { mn = fminf(mn, redf[i]); mx = fmaxf(mx, redf2[i]); }
            s_dmin = mn; s_dmax = mx;
        }
    }

    for (int i = t; i < 512; i += TPB) hist[i] = 0;
    if (t == 0) s_ncand = 0;
    __syncthreads();
    float dmin = s_dmin, dmax = s_dmax;
    float scale = (dmax > dmin) ? 511.0f / (dmax - dmin) : 0.0f;
    for (int m = t; m < NN; m += TPB) {
        float d = __uint_as_float((unsigned)(key[m] >> 11));
        int bin = min((int)((d - dmin) * scale), 511);
        atomicAdd(&hist[bin], 1);
    }
    __syncthreads();
    if (t == 0) {
        int cum = 0, bs = 511;
        for (int i = 0; i < 512; i++) { cum += hist[i]; if (cum >= TOPK) { bs = i; break; } }
        s_bstar = bs;
    }
    __syncthreads();
    int bs = s_bstar;

    // compact candidates (bin <= bs): binning is value-monotone, so candidate
    // rank among candidates == global rank.
    for (int m = t; m < NN; m += TPB) {
        u64 kk = key[m];
        float d = __uint_as_float((unsigned)(kk >> 11));
        int bin = min((int)((d - dmin) * scale), 511);
        if (bin <= bs) { int pos = atomicAdd(&s_ncand, 1); cand[pos] = kk; }
    }
    __syncthreads();
    int nc = s_ncand;

    // exact stable rank among candidates (== jax.lax.top_k order); emit top-110
    for (int ci = t; ci < nc; ci += TPB) {
        u64 kn = cand[ci];
        int r = 0;
        for (int j = 0; j < nc; j++) r += (int)(cand[j] < kn);
        if (r < TOPK) {
            int m = (int)(kn & 2047u);
            const float* p = base_in + m * 3;
            float* o = out + (b * TOPK + r) * 3;
            o[0] = p[0]; o[1] = p[1]; o[2] = p[2];
        }
    }
}

// ---------------------------------------------------------------------------
extern "C" void kernel_launch(void* const* d_in, const int* in_sizes, int n_in,
                              void* d_out, int out_size) {
    const float* in_mat = (const float*)d_in[0];
    const float* Wi = (const float*)d_in[1];
    const float* bi = (const float*)d_in[2];
    const float* Wq = (const float*)d_in[3];
    const float* bq = (const float*)d_in[4];
    const float* Wk = (const float*)d_in[5];
    // bk (d_in[6]) cancels in softmax; d_in[7..10] (Wv,bv,Wo,bo) are dead.
    float* out = (float*)d_out;

    fused_kernel<<<dim3(NCHUNK, BB), TPB>>>(in_mat, Wi, bi, Wq, bq, Wk, out);
}

// round 10
// speedup vs baseline: 1.0417x; 1.0417x over previous
#include <cuda_runtime.h>

#define BB 32
#define NN 2000
#define DD 5
#define GRP 5
#define TOPK 110
#define TPB 256
#define NCHUNK 9
#define CHUNK 223

typedef unsigned long long u64;

__device__ float g_diag[BB * NN];
__device__ unsigned int g_cnt[BB];   // monotonic; each launch adds exactly NCHUNK per batch

// ---- PTX helpers ----------------------------------------------------------
__device__ __forceinline__ float ex2(float x) {
    float y; asm("ex2.approx.ftz.f32 %0, %1;" : "=f"(y) : "f"(x)); return y;
}
__device__ __forceinline__ u64 pk(float lo, float hi) {
    u64 r; asm("mov.b64 %0, {%1, %2};" : "=l"(r) : "f"(lo), "f"(hi)); return r;
}
__device__ __forceinline__ float2 up(u64 v) {
    float2 r; asm("mov.b64 {%0, %1}, %2;" : "=f"(r.x), "=f"(r.y) : "l"(v)); return r;
}
__device__ __forceinline__ u64 fma2(u64 a, u64 b, u64 c) {
    u64 d; asm("fma.rn.f32x2 %0, %1, %2, %3;" : "=l"(d) : "l"(a), "l"(b), "l"(c)); return d;
}

// ---------------------------------------------------------------------------
// Fused kernel. grid = (9, 32), block = 256  (R6 layout).
// score(n,m)*log2e = alpha_n . in[m] + const_n  (const cancels in softmax),
// alpha_n = (log2e/sqrt(5)) * Wi (Wk q_n)  -- 3-dim.
// Z: fp32-exact v -> cvt f16x2 -> ex2.approx.f16x2 (2 exps / MUFU op),
// 4 independent f16x2 accumulator chains, flushed to fp32 every 40 points
// (per-lane <=5 adds of terms <=1: shallower than the passing R7 variant).
//
// smem sbuf (34048 B):
//   diag phase : P0 f32[2000] @0, P1 @8000, P2 @16000  (transposed in_mat[b])
//   select phase (overlay, last-arriving block only):
//     key u64[2000] @0, hist int[512] @16000, cand u64[2000] @18048
// ---------------------------------------------------------------------------
__global__ void __launch_bounds__(TPB, 2) fused_kernel(
    const float* __restrict__ in_mat,
    const float* __restrict__ Wi, const float* __restrict__ bi,
    const float* __restrict__ Wq, const float* __restrict__ bq,
    const float* __restrict__ Wk,
    float* __restrict__ out)
{
    __shared__ __align__(16) char sbuf[34048];
    __shared__ float wsm[75];   // 0:Wi(15) 15:bi(5) 20:Wq(25) 45:bq(5) 50:Wk(25)
    __shared__ float redf[8];
    __shared__ float redf2[8];
    __shared__ int   redi[8];
    __shared__ float cen[3];
    __shared__ int s_ncand, s_bstar, s_last;
    __shared__ float s_dmin, s_dmax;

    const int b = blockIdx.y, c = blockIdx.x, t = threadIdx.x;
    const float* base_in = in_mat + b * NN * 3;

    float* P0 = (float*)(sbuf);
    float* P1 = (float*)(sbuf + 8000);
    float* P2 = (float*)(sbuf + 16000);

    // ---- stage weights ----
    if (t < 15)      wsm[t] = Wi[t];
    else if (t < 20) wsm[t] = bi[t - 15];
    else if (t < 45) wsm[t] = Wq[t - 20];
    else if (t < 50) wsm[t] = bq[t - 45];
    else if (t < 75) wsm[t] = Wk[t - 50];
    __syncthreads();

    // ---- phase 1: transpose in_mat[b] -> SoA smem, track max ||in||^2 ----
    float bmax = 0.0f;
    for (int p = t; p < NN; p += TPB) {
        float i0 = base_in[p * 3], i1 = base_in[p * 3 + 1], i2 = base_in[p * 3 + 2];
        P0[p] = i0; P1[p] = i1; P2[p] = i2;
        bmax = fmaxf(bmax, fmaf(i0, i0, fmaf(i1, i1, i2 * i2)));
    }
#pragma unroll
    for (int o = 16; o; o >>= 1) bmax = fmaxf(bmax, __shfl_xor_sync(0xffffffffu, bmax, o));
    if ((t & 31) == 0) redf[t >> 5] = bmax;
    __syncthreads();
    float maxn2 = redf[0];
#pragma unroll
    for (int i = 1; i < 8; i++) maxn2 = fmaxf(maxn2, redf[i]);

    // ---- phase 2: alpha_n, then branchless diag softmax over raw inputs ----
    const int n = c * CHUNK + t;
    if (t < CHUNK && n < NN) {
        float i0 = base_in[n * 3], i1 = base_in[n * 3 + 1], i2 = base_in[n * 3 + 2];
        float x[DD];
#pragma unroll
        for (int j = 0; j < DD; j++)
            x[j] = fmaf(i0, wsm[j], fmaf(i1, wsm[5 + j], fmaf(i2, wsm[10 + j], wsm[15 + j])));
        float q[DD];
#pragma unroll
        for (int j = 0; j < DD; j++) {
            float qq = wsm[45 + j];
#pragma unroll
            for (int d = 0; d < DD; d++) qq = fmaf(x[d], wsm[20 + d * 5 + j], qq);
            q[j] = qq;
        }
        float wkq[DD];
#pragma unroll
        for (int d = 0; d < DD; d++) {
            float s = 0.f;
#pragma unroll
            for (int j = 0; j < DD; j++) s = fmaf(wsm[50 + d * 5 + j], q[j], s);
            wkq[d] = s;
        }
        const float qscale = 1.4426950408889634f / 2.2360679774997896f; // log2e/sqrt(5)
        float a0 = 0.f, a1 = 0.f, a2 = 0.f;
#pragma unroll
        for (int d = 0; d < DD; d++) {
            a0 = fmaf(wsm[0 + d], wkq[d], a0);
            a1 = fmaf(wsm[5 + d], wkq[d], a1);
            a2 = fmaf(wsm[10 + d], wkq[d], a2);
        }
        a0 *= qscale; a1 *= qscale; a2 *= qscale;

        // shift >= max_m alpha . in[m]  (Cauchy-Schwarz) -> all ex2 args <= 0
        float shift = sqrtf(fmaf(a0, a0, fmaf(a1, a1, a2 * a2))) * sqrtf(maxn2);

        u64 ax = pk(a0, a0), ay = pk(a1, a1), az = pk(a2, a2);
        u64 ns = pk(-shift, -shift);

        const ulonglong2* Q0 = (const ulonglong2*)P0;
        const ulonglong2* Q1 = (const ulonglong2*)P1;
        const ulonglong2* Q2 = (const ulonglong2*)P2;

        float zA = 0.f, zB = 0.f, zC = 0.f, zD = 0.f;
        // 50 groups x 40 points; inner 10 iters fully unrolled, outer free.
        for (int o = 0; o < 50; o++) {
            unsigned accs0 = 0, accs1 = 0, accs2 = 0, accs3 = 0;  // f16x2 partials
#pragma unroll
            for (int i = 0; i < 10; i++) {
                int p = o * 10 + i;
                ulonglong2 A0 = Q0[p], A1 = Q1[p], A2 = Q2[p];
                u64 v0 = fma2(ax, A0.x, ns);
                v0 = fma2(ay, A1.x, v0);
                v0 = fma2(az, A2.x, v0);
                u64 v1 = fma2(ax, A0.y, ns);
                v1 = fma2(ay, A1.y, v1);
                v1 = fma2(az, A2.y, v1);
                float2 f0 = up(v0), f1 = up(v1);
                unsigned h0, h1, e0, e1;
                asm("cvt.rn.f16x2.f32 %0, %1, %2;" : "=r"(h0) : "f"(f0.y), "f"(f0.x));
                asm("cvt.rn.f16x2.f32 %0, %1, %2;" : "=r"(h1) : "f"(f1.y), "f"(f1.x));
                asm("ex2.approx.f16x2 %0, %1;" : "=r"(e0) : "r"(h0));
                asm("ex2.approx.f16x2 %0, %1;" : "=r"(e1) : "r"(h1));
                if (i & 1) {
                    asm("add.rn.f16x2 %0, %0, %1;" : "+r"(accs2) : "r"(e0));
                    asm("add.rn.f16x2 %0, %0, %1;" : "+r"(accs3) : "r"(e1));
                } else {
                    asm("add.rn.f16x2 %0, %0, %1;" : "+r"(accs0) : "r"(e0));
                    asm("add.rn.f16x2 %0, %0, %1;" : "+r"(accs1) : "r"(e1));
                }
            }
            // flush f16x2 partials to fp32 (4 independent chains)
            float l0, h0f, l1, h1f, l2, h2f, l3, h3f;
            asm("{.reg .b16 l,h; mov.b32 {l,h}, %2; cvt.f32.f16 %0,l; cvt.f32.f16 %1,h;}"
                : "=f"(l0), "=f"(h0f) : "r"(accs0));
            asm("{.reg .b16 l,h; mov.b32 {l,h}, %2; cvt.f32.f16 %0,l; cvt.f32.f16 %1,h;}"
                : "=f"(l1), "=f"(h1f) : "r"(accs1));
            asm("{.reg .b16 l,h; mov.b32 {l,h}, %2; cvt.f32.f16 %0,l; cvt.f32.f16 %1,h;}"
                : "=f"(l2), "=f"(h2f) : "r"(accs2));
            asm("{.reg .b16 l,h; mov.b32 {l,h}, %2; cvt.f32.f16 %0,l; cvt.f32.f16 %1,h;}"
                : "=f"(l3), "=f"(h3f) : "r"(accs3));
            zA += l0 + h0f;
            zB += l1 + h1f;
            zC += l2 + h2f;
            zD += l3 + h3f;
        }
        float zsum = (zA + zB) + (zC + zD);

        float vn = fmaf(a0, i0, fmaf(a1, i1, a2 * i2)) - shift;   // fp32-exact numerator
        g_diag[b * NN + n] = ex2(vn) / zsum;
    }

    // ---- arrival: last block of batch b runs selection ----
    __threadfence();
    __syncthreads();
    if (t == 0) {
        unsigned old = atomicAdd(&g_cnt[b], 1u);
        s_last = ((old % NCHUNK) == NCHUNK - 1) ? 1 : 0;
    }
    __syncthreads();
    if (!s_last) return;
    __threadfence();

    // ================= selection (one block per batch) ====================
    const float* db = g_diag + b * NN;

    // group sums + argmax (first-max tie-break == jnp.argmax)
    {
        float bv = -1e30f; int gi = 1 << 30;
        for (int g = t; g < NN / GRP; g += TPB) {
            const float* d5 = db + g * GRP;
            float s = d5[0] + d5[1] + d5[2] + d5[3] + d5[4];
            if (s > bv) { bv = s; gi = g; }
        }
#pragma unroll
        for (int o = 16; o; o >>= 1) {
            float ov = __shfl_xor_sync(0xffffffffu, bv, o);
            int   oi = __shfl_xor_sync(0xffffffffu, gi, o);
            if (ov > bv || (ov == bv && oi < gi)) { bv = ov; gi = oi; }
        }
        if ((t & 31) == 0) { redf[t >> 5] = bv; redi[t >> 5] = gi; }
        __syncthreads();
        if (t == 0) {
            float v = redf[0]; int gi2 = redi[0];
#pragma unroll
            for (int i = 1; i < 8; i++)
                if (redf[i] > v || (redf[i] == v && redi[i] < gi2)) { v = redf[i]; gi2 = redi[i]; }
            const float* gp = base_in + gi2 * GRP * 3;
            float cx = 0.f, cy = 0.f, cz = 0.f;
#pragma unroll
            for (int p = 0; p < GRP; p++) {
                cx += gp[p * 3 + 0]; cy += gp[p * 3 + 1]; cz += gp[p * 3 + 2];
            }
            cen[0] = cx * 0.2f; cen[1] = cy * 0.2f; cen[2] = cz * 0.2f;
        }
        __syncthreads();
    }

    u64* key  = (u64*)sbuf;
    int* hist = (int*)(sbuf + 16000);
    u64* cand = (u64*)(sbuf + 18048);

    // distances -> keys, min/max reduction
    {
        float cx = cen[0], cy = cen[1], cz = cen[2];
        float dmin = 1e30f, dmax = 0.0f;
        for (int m = t; m < NN; m += TPB) {
            const float* p = base_in + m * 3;
            float dx = p[0] - cx, dy = p[1] - cy, dz = p[2] - cz;
            float d = sqrtf(fmaf(dx, dx, fmaf(dy, dy, dz * dz)));
            key[m] = (((u64)__float_as_uint(d)) << 11) | (unsigned)m;
            dmin = fminf(dmin, d); dmax = fmaxf(dmax, d);
        }
#pragma unroll
        for (int o = 16; o; o >>= 1) {
            dmin = fminf(dmin, __shfl_xor_sync(0xffffffffu, dmin, o));
            dmax = fmaxf(dmax, __shfl_xor_sync(0xffffffffu, dmax, o));
        }
        if ((t & 31) == 0) { redf[t >> 5] = dmin; redf2[t >> 5] = dmax; }
        __syncthreads();
        if (t == 0) {
            float mn = redf[0], mx = redf2[0];
#pragma unroll
            for (int i = 1; i < 8; i++) { mn = fminf(mn, redf[i]); mx = fmaxf(mx, redf2[i]); }
            s_dmin = mn; s_dmax = mx;
        }
    }

    for (int i = t; i < 512; i += TPB) hist[i] = 0;
    if (t == 0) s_ncand = 0;
    __syncthreads();
    float dmin = s_dmin, dmax = s_dmax;
    float scale = (dmax > dmin) ? 511.0f / (dmax - dmin) : 0.0f;
    for (int m = t; m < NN; m += TPB) {
        float d = __uint_as_float((unsigned)(key[m] >> 11));
        int bin = min((int)((d - dmin) * scale), 511);
        atomicAdd(&hist[bin], 1);
    }
    __syncthreads();
    if (t == 0) {
        int cum = 0, bs = 511;
        for (int i = 0; i < 512; i++) { cum += hist[i]; if (cum >= TOPK) { bs = i; break; } }
        s_bstar = bs;
    }
    __syncthreads();
    int bs = s_bstar;

    // compact candidates (bin <= bs): binning is value-monotone, so candidate
    // rank among candidates == global rank.
    for (int m = t; m < NN; m += TPB) {
        u64 kk = key[m];
        float d = __uint_as_float((unsigned)(kk >> 11));
        int bin = min((int)((d - dmin) * scale), 511);
        if (bin <= bs) { int pos = atomicAdd(&s_ncand, 1); cand[pos] = kk; }
    }
    __syncthreads();
    int nc = s_ncand;

    // exact stable rank among candidates (== jax.lax.top_k order); emit top-110
    for (int ci = t; ci < nc; ci += TPB) {
        u64 kn = cand[ci];
        int r = 0;
        for (int j = 0; j < nc; j++) r += (int)(cand[j] < kn);
        if (r < TOPK) {
            int m = (int)(kn & 2047u);
            const float* p = base_in + m * 3;
            float* o = out + (b * TOPK + r) * 3;
            o[0] = p[0]; o[1] = p[1]; o[2] = p[2];
        }
    }
}

// ---------------------------------------------------------------------------
extern "C" void kernel_launch(void* const* d_in, const int* in_sizes, int n_in,
                              void* d_out, int out_size) {
    const float* in_mat = (const float*)d_in[0];
    const float* Wi = (const float*)d_in[1];
    const float* bi = (const float*)d_in[2];
    const float* Wq = (const float*)d_in[3];
    const float* bq = (const float*)d_in[4];
    const float* Wk = (const float*)d_in[5];
    // bk (d_in[6]) cancels in softmax; d_in[7..10] (Wv,bv,Wo,bo) are dead.
    float* out = (float*)d_out;

    fused_kernel<<<dim3(NCHUNK, BB), TPB>>>(in_mat, Wi, bi, Wq, bq, Wk, out);
}

// round 11
// speedup vs baseline: 1.2119x; 1.1634x over previous
#include <cuda_runtime.h>

#define BB 32
#define NN 2000
#define DD 5
#define GRP 5
#define TOPK 110
#define TPB 256
#define NCHUNK 9
#define CHUNK 223

typedef unsigned long long u64;

__device__ float g_diag[BB * NN];
__device__ unsigned int g_cnt[BB];   // monotonic; each launch adds exactly NCHUNK per batch

// ---- PTX helpers ----------------------------------------------------------
__device__ __forceinline__ float ex2(float x) {
    float y; asm("ex2.approx.ftz.f32 %0, %1;" : "=f"(y) : "f"(x)); return y;
}
__device__ __forceinline__ unsigned f2h2(float lo, float hi) {
    unsigned r; asm("cvt.rn.f16x2.f32 %0, %1, %2;" : "=r"(r) : "f"(hi), "f"(lo)); return r;
}
__device__ __forceinline__ unsigned hfma2_(unsigned a, unsigned b, unsigned c) {
    unsigned d; asm("fma.rn.f16x2 %0, %1, %2, %3;" : "=r"(d) : "r"(a), "r"(b), "r"(c)); return d;
}
__device__ __forceinline__ unsigned ex2h2(unsigned a) {
    unsigned d; asm("ex2.approx.f16x2 %0, %1;" : "=r"(d) : "r"(a)); return d;
}
__device__ __forceinline__ unsigned hadd2_(unsigned a, unsigned b) {
    unsigned d; asm("add.rn.f16x2 %0, %1, %2;" : "=r"(d) : "r"(a), "r"(b)); return d;
}
__device__ __forceinline__ float h2sum(unsigned a) {
    float lo, hi;
    asm("{.reg .b16 l,h; mov.b32 {l,h}, %2; cvt.f32.f16 %0,l; cvt.f32.f16 %1,h;}"
        : "=f"(lo), "=f"(hi) : "r"(a));
    return lo + hi;
}

// ---------------------------------------------------------------------------
// Fused kernel. grid = (9, 32), block = 256  (R6 layout).
// score(n,m)*log2e = alpha_n . in[m] + const_n  (const cancels in softmax),
// alpha_n = (log2e/sqrt(5)) * Wi (Wk q_n)  -- 3-dim.
// Points stored in smem as PACKED f16 (converted once at staging); the Z loop
// runs entirely in f16x2: 3 LDS.128 + 12 HFMA2 + 4 ex2.f16x2 + 4 HADD2 per
// 8 points -- no conversions in the loop. fp32-exact numerator.
//
// smem sbuf (34048 B):
//   diag phase : H0 h2[1000] @0 (4000B), H1 @4000, H2 @8000  (f16 transposed pts)
//   select phase (overlay, last-arriving block only):
//     key u64[2000] @0, hist int[512] @16000, cand u64[2000] @18048
// ---------------------------------------------------------------------------
__global__ void __launch_bounds__(TPB, 2) fused_kernel(
    const float* __restrict__ in_mat,
    const float* __restrict__ Wi, const float* __restrict__ bi,
    const float* __restrict__ Wq, const float* __restrict__ bq,
    const float* __restrict__ Wk,
    float* __restrict__ out)
{
    __shared__ __align__(16) char sbuf[34048];
    __shared__ float wsm[75];   // 0:Wi(15) 15:bi(5) 20:Wq(25) 45:bq(5) 50:Wk(25)
    __shared__ float redf[8];
    __shared__ float redf2[8];
    __shared__ int   redi[8];
    __shared__ float cen[3];
    __shared__ int s_ncand, s_bstar, s_last;
    __shared__ float s_dmin, s_dmax;

    const int b = blockIdx.y, c = blockIdx.x, t = threadIdx.x;
    const float* base_in = in_mat + b * NN * 3;

    unsigned* H0 = (unsigned*)(sbuf);          // half2 pairs, comp 0
    unsigned* H1 = (unsigned*)(sbuf + 4000);
    unsigned* H2 = (unsigned*)(sbuf + 8000);

    // ---- stage weights ----
    if (t < 15)      wsm[t] = Wi[t];
    else if (t < 20) wsm[t] = bi[t - 15];
    else if (t < 45) wsm[t] = Wq[t - 20];
    else if (t < 50) wsm[t] = bq[t - 45];
    else if (t < 75) wsm[t] = Wk[t - 50];
    __syncthreads();

    // ---- phase 1: pack in_mat[b] as f16 SoA pairs; track max ||in||^2 ----
    float bmax = 0.0f;
    for (int pp = t; pp < NN / 2; pp += TPB) {
        const float* pe = base_in + (2 * pp) * 3;
        float e0 = pe[0], e1 = pe[1], e2 = pe[2];
        float o0 = pe[3], o1 = pe[4], o2 = pe[5];
        H0[pp] = f2h2(e0, o0);
        H1[pp] = f2h2(e1, o1);
        H2[pp] = f2h2(e2, o2);
        float ne = fmaf(e0, e0, fmaf(e1, e1, e2 * e2));
        float no = fmaf(o0, o0, fmaf(o1, o1, o2 * o2));
        bmax = fmaxf(bmax, fmaxf(ne, no));
    }
#pragma unroll
    for (int o = 16; o; o >>= 1) bmax = fmaxf(bmax, __shfl_xor_sync(0xffffffffu, bmax, o));
    if ((t & 31) == 0) redf[t >> 5] = bmax;
    __syncthreads();
    float maxn2 = redf[0];
#pragma unroll
    for (int i = 1; i < 8; i++) maxn2 = fmaxf(maxn2, redf[i]);

    // ---- phase 2: alpha_n, then branchless f16 diag softmax ----
    const int n = c * CHUNK + t;
    if (t < CHUNK && n < NN) {
        float i0 = base_in[n * 3], i1 = base_in[n * 3 + 1], i2 = base_in[n * 3 + 2];
        float x[DD];
#pragma unroll
        for (int j = 0; j < DD; j++)
            x[j] = fmaf(i0, wsm[j], fmaf(i1, wsm[5 + j], fmaf(i2, wsm[10 + j], wsm[15 + j])));
        float q[DD];
#pragma unroll
        for (int j = 0; j < DD; j++) {
            float qq = wsm[45 + j];
#pragma unroll
            for (int d = 0; d < DD; d++) qq = fmaf(x[d], wsm[20 + d * 5 + j], qq);
            q[j] = qq;
        }
        float wkq[DD];
#pragma unroll
        for (int d = 0; d < DD; d++) {
            float s = 0.f;
#pragma unroll
            for (int j = 0; j < DD; j++) s = fmaf(wsm[50 + d * 5 + j], q[j], s);
            wkq[d] = s;
        }
        const float qscale = 1.4426950408889634f / 2.2360679774997896f; // log2e/sqrt(5)
        float a0 = 0.f, a1 = 0.f, a2 = 0.f;
#pragma unroll
        for (int d = 0; d < DD; d++) {
            a0 = fmaf(wsm[0 + d], wkq[d], a0);
            a1 = fmaf(wsm[5 + d], wkq[d], a1);
            a2 = fmaf(wsm[10 + d], wkq[d], a2);
        }
        a0 *= qscale; a1 *= qscale; a2 *= qscale;

        // shift >= max_m alpha . in[m]  (Cauchy-Schwarz) -> args ~<= 0
        float shift = sqrtf(fmaf(a0, a0, fmaf(a1, a1, a2 * a2))) * sqrtf(maxn2);

        unsigned ah0 = f2h2(a0, a0), ah1 = f2h2(a1, a1), ah2 = f2h2(a2, a2);
        unsigned nsh = f2h2(-shift, -shift);

        const uint4* G0 = (const uint4*)H0;    // 250 groups of 8 points
        const uint4* G1 = (const uint4*)H1;
        const uint4* G2 = (const uint4*)H2;

        float zA = 0.f, zB = 0.f, zC = 0.f, zD = 0.f;
        for (int o = 0; o < 25; o++) {
            unsigned acc0 = 0, acc1 = 0, acc2 = 0, acc3 = 0;   // f16x2 partials
#pragma unroll
            for (int i = 0; i < 10; i++) {
                int p = o * 10 + i;
                uint4 x0 = G0[p], x1 = G1[p], x2 = G2[p];
                unsigned v;
                v = hfma2_(ah2, x2.x, nsh);
                v = hfma2_(ah1, x1.x, v);
                v = hfma2_(ah0, x0.x, v);
                acc0 = hadd2_(acc0, ex2h2(v));
                v = hfma2_(ah2, x2.y, nsh);
                v = hfma2_(ah1, x1.y, v);
                v = hfma2_(ah0, x0.y, v);
                acc1 = hadd2_(acc1, ex2h2(v));
                v = hfma2_(ah2, x2.z, nsh);
                v = hfma2_(ah1, x1.z, v);
                v = hfma2_(ah0, x0.z, v);
                acc2 = hadd2_(acc2, ex2h2(v));
                v = hfma2_(ah2, x2.w, nsh);
                v = hfma2_(ah1, x1.w, v);
                v = hfma2_(ah0, x0.w, v);
                acc3 = hadd2_(acc3, ex2h2(v));
            }
            zA += h2sum(acc0);
            zB += h2sum(acc1);
            zC += h2sum(acc2);
            zD += h2sum(acc3);
        }
        float zsum = (zA + zB) + (zC + zD);

        float vn = fmaf(a0, i0, fmaf(a1, i1, a2 * i2)) - shift;   // fp32-exact numerator
        g_diag[b * NN + n] = ex2(vn) / zsum;
    }

    // ---- arrival: last block of batch b runs selection ----
    __threadfence();
    __syncthreads();
    if (t == 0) {
        unsigned old = atomicAdd(&g_cnt[b], 1u);
        s_last = ((old % NCHUNK) == NCHUNK - 1) ? 1 : 0;
    }
    __syncthreads();
    if (!s_last) return;
    __threadfence();

    // ================= selection (one block per batch) ====================
    const float* db = g_diag + b * NN;

    // group sums + argmax (first-max tie-break == jnp.argmax)
    {
        float bv = -1e30f; int gi = 1 << 30;
        for (int g = t; g < NN / GRP; g += TPB) {
            const float* d5 = db + g * GRP;
            float s = d5[0] + d5[1] + d5[2] + d5[3] + d5[4];
            if (s > bv) { bv = s; gi = g; }
        }
#pragma unroll
        for (int o = 16; o; o >>= 1) {
            float ov = __shfl_xor_sync(0xffffffffu, bv, o);
            int   oi = __shfl_xor_sync(0xffffffffu, gi, o);
            if (ov > bv || (ov == bv && oi < gi)) { bv = ov; gi = oi; }
        }
        if ((t & 31) == 0) { redf[t >> 5] = bv; redi[t >> 5] = gi; }
        __syncthreads();
        if (t == 0) {
            float v = redf[0]; int gi2 = redi[0];
#pragma unroll
            for (int i = 1; i < 8; i++)
                if (redf[i] > v || (redf[i] == v && redi[i] < gi2)) { v = redf[i]; gi2 = redi[i]; }
            const float* gp = base_in + gi2 * GRP * 3;
            float cx = 0.f, cy = 0.f, cz = 0.f;
#pragma unroll
            for (int p = 0; p < GRP; p++) {
                cx += gp[p * 3 + 0]; cy += gp[p * 3 + 1]; cz += gp[p * 3 + 2];
            }
            cen[0] = cx * 0.2f; cen[1] = cy * 0.2f; cen[2] = cz * 0.2f;
        }
        __syncthreads();
    }

    u64* key  = (u64*)sbuf;
    int* hist = (int*)(sbuf + 16000);
    u64* cand = (u64*)(sbuf + 18048);

    // distances -> keys, min/max reduction
    {
        float cx = cen[0], cy = cen[1], cz = cen[2];
        float dmin = 1e30f, dmax = 0.0f;
        for (int m = t; m < NN; m += TPB) {
            const float* p = base_in + m * 3;
            float dx = p[0] - cx, dy = p[1] - cy, dz = p[2] - cz;
            float d = sqrtf(fmaf(dx, dx, fmaf(dy, dy, dz * dz)));
            key[m] = (((u64)__float_as_uint(d)) << 11) | (unsigned)m;
            dmin = fminf(dmin, d); dmax = fmaxf(dmax, d);
        }
#pragma unroll
        for (int o = 16; o; o >>= 1) {
            dmin = fminf(dmin, __shfl_xor_sync(0xffffffffu, dmin, o));
            dmax = fmaxf(dmax, __shfl_xor_sync(0xffffffffu, dmax, o));
        }
        if ((t & 31) == 0) { redf[t >> 5] = dmin; redf2[t >> 5] = dmax; }
        __syncthreads();
        if (t == 0) {
            float mn = redf[0], mx = redf2[0];
#pragma unroll
            for (int i = 1; i < 8; i++) { mn = fminf(mn, redf[i]); mx = fmaxf(mx, redf2[i]); }
            s_dmin = mn; s_dmax = mx;
        }
    }

    for (int i = t; i < 512; i += TPB) hist[i] = 0;
    if (t == 0) s_ncand = 0;
    __syncthreads();
    float dmin = s_dmin, dmax = s_dmax;
    float scale = (dmax > dmin) ? 511.0f / (dmax - dmin) : 0.0f;
    for (int m = t; m < NN; m += TPB) {
        float d = __uint_as_float((unsigned)(key[m] >> 11));
        int bin = min((int)((d - dmin) * scale), 511);
        atomicAdd(&hist[bin], 1);
    }
    __syncthreads();
    if (t == 0) {
        int cum = 0, bs = 511;
        for (int i = 0; i < 512; i++) { cum += hist[i]; if (cum >= TOPK) { bs = i; break; } }
        s_bstar = bs;
    }
    __syncthreads();
    int bs = s_bstar;

    // compact candidates (bin <= bs): binning is value-monotone, so candidate
    // rank among candidates == global rank.
    for (int m = t; m < NN; m += TPB) {
        u64 kk = key[m];
        float d = __uint_as_float((unsigned)(kk >> 11));
        int bin = min((int)((d - dmin) * scale), 511);
        if (bin <= bs) { int pos = atomicAdd(&s_ncand, 1); cand[pos] = kk; }
    }
    __syncthreads();
    int nc = s_ncand;

    // exact stable rank among candidates (== jax.lax.top_k order); emit top-110
    for (int ci = t; ci < nc; ci += TPB) {
        u64 kn = cand[ci];
        int r = 0;
        for (int j = 0; j < nc; j++) r += (int)(cand[j] < kn);
        if (r < TOPK) {
            int m = (int)(kn & 2047u);
            const float* p = base_in + m * 3;
            float* o = out + (b * TOPK + r) * 3;
            o[0] = p[0]; o[1] = p[1]; o[2] = p[2];
        }
    }
}

// ---------------------------------------------------------------------------
extern "C" void kernel_launch(void* const* d_in, const int* in_sizes, int n_in,
                              void* d_out, int out_size) {
    const float* in_mat = (const float*)d_in[0];
    const float* Wi = (const float*)d_in[1];
    const float* bi = (const float*)d_in[2];
    const float* Wq = (const float*)d_in[3];
    const float* bq = (const float*)d_in[4];
    const float* Wk = (const float*)d_in[5];
    // bk (d_in[6]) cancels in softmax; d_in[7..10] (Wv,bv,Wo,bo) are dead.
    float* out = (float*)d_out;

    fused_kernel<<<dim3(NCHUNK, BB), TPB>>>(in_mat, Wi, bi, Wq, bq, Wk, out);
}

// round 12
// speedup vs baseline: 1.2703x; 1.0482x over previous
#include <cuda_runtime.h>

#define BB 32
#define NN 2000
#define DD 5
#define GRP 5
#define TOPK 110
#define TPB 256
#define NCHUNK 18
#define CHUNK 112          // n's per block; 2 threads per n (m-range split 1040/960)

typedef unsigned long long u64;

__device__ float g_diag[BB * NN];
__device__ unsigned int g_cnt[BB];   // monotonic; each launch adds exactly NCHUNK per batch

// ---- PTX helpers ----------------------------------------------------------
__device__ __forceinline__ float ex2(float x) {
    float y; asm("ex2.approx.ftz.f32 %0, %1;" : "=f"(y) : "f"(x)); return y;
}
__device__ __forceinline__ unsigned f2h2(float lo, float hi) {
    unsigned r; asm("cvt.rn.f16x2.f32 %0, %1, %2;" : "=r"(r) : "f"(hi), "f"(lo)); return r;
}
__device__ __forceinline__ unsigned hfma2_(unsigned a, unsigned b, unsigned c) {
    unsigned d; asm("fma.rn.f16x2 %0, %1, %2, %3;" : "=r"(d) : "r"(a), "r"(b), "r"(c)); return d;
}
__device__ __forceinline__ unsigned ex2h2(unsigned a) {
    unsigned d; asm("ex2.approx.f16x2 %0, %1;" : "=r"(d) : "r"(a)); return d;
}
__device__ __forceinline__ unsigned hadd2_(unsigned a, unsigned b) {
    unsigned d; asm("add.rn.f16x2 %0, %1, %2;" : "=r"(d) : "r"(a), "r"(b)); return d;
}
__device__ __forceinline__ float h2sum(unsigned a) {
    float lo, hi;
    asm("{.reg .b16 l,h; mov.b32 {l,h}, %2; cvt.f32.f16 %0,l; cvt.f32.f16 %1,h;}"
        : "=f"(lo), "=f"(hi) : "r"(a));
    return lo + hi;
}

// ---------------------------------------------------------------------------
// Fused kernel. grid = (18, 32), block = 256, target 4 blocks/SM.
// score(n,m)*log2e = alpha_n . in[m] + const_n  (const cancels in softmax),
// alpha_n = (log2e/sqrt(5)) * Wi (Wk q_n)  -- 3-dim.
// TWO threads per n: t (<112) sums m-groups [0,130), t+112 sums [130,250)
// (uint4 groups of 8 points; 1040/960 split keeps both multiples of the
// 10-iter unroll). Both compute identical alpha/shift; partials combined in
// smem. Points stored packed f16 (staged once); loop is pure f16x2.
//
// smem sbuf (34048 B):
//   diag phase : H0 h2[1000] @0 (4000B), H1 @4000, H2 @8000
//   select phase (overlay, last-arriving block only):
//     key u64[2000] @0, hist int[512] @16000, cand u64[2000] @18048
// ---------------------------------------------------------------------------
__global__ void __launch_bounds__(TPB, 4) fused_kernel(
    const float* __restrict__ in_mat,
    const float* __restrict__ Wi, const float* __restrict__ bi,
    const float* __restrict__ Wq, const float* __restrict__ bq,
    const float* __restrict__ Wk,
    float* __restrict__ out)
{
    __shared__ __align__(16) char sbuf[34048];
    __shared__ float wsm[75];   // 0:Wi(15) 15:bi(5) 20:Wq(25) 45:bq(5) 50:Wk(25)
    __shared__ float partial[2 * CHUNK];
    __shared__ float redf[8];
    __shared__ float redf2[8];
    __shared__ int   redi[8];
    __shared__ float cen[3];
    __shared__ int s_ncand, s_bstar, s_last;
    __shared__ float s_dmin, s_dmax;

    const int b = blockIdx.y, c = blockIdx.x, t = threadIdx.x;
    const float* base_in = in_mat + b * NN * 3;

    unsigned* H0 = (unsigned*)(sbuf);          // half2 pairs, comp 0
    unsigned* H1 = (unsigned*)(sbuf + 4000);
    unsigned* H2 = (unsigned*)(sbuf + 8000);

    // ---- stage weights ----
    if (t < 15)      wsm[t] = Wi[t];
    else if (t < 20) wsm[t] = bi[t - 15];
    else if (t < 45) wsm[t] = Wq[t - 20];
    else if (t < 50) wsm[t] = bq[t - 45];
    else if (t < 75) wsm[t] = Wk[t - 50];
    __syncthreads();

    // ---- phase 1: pack in_mat[b] as f16 SoA pairs; track max ||in||^2 ----
    float bmax = 0.0f;
    for (int pp = t; pp < NN / 2; pp += TPB) {
        const float* pe = base_in + (2 * pp) * 3;
        float e0 = pe[0], e1 = pe[1], e2 = pe[2];
        float o0 = pe[3], o1 = pe[4], o2 = pe[5];
        H0[pp] = f2h2(e0, o0);
        H1[pp] = f2h2(e1, o1);
        H2[pp] = f2h2(e2, o2);
        float ne = fmaf(e0, e0, fmaf(e1, e1, e2 * e2));
        float no = fmaf(o0, o0, fmaf(o1, o1, o2 * o2));
        bmax = fmaxf(bmax, fmaxf(ne, no));
    }
#pragma unroll
    for (int o = 16; o; o >>= 1) bmax = fmaxf(bmax, __shfl_xor_sync(0xffffffffu, bmax, o));
    if ((t & 31) == 0) redf[t >> 5] = bmax;
    __syncthreads();
    float maxn2 = redf[0];
#pragma unroll
    for (int i = 1; i < 8; i++) maxn2 = fmaxf(maxn2, redf[i]);

    // ---- phase 2: alpha_n; two threads per n, split m-range ----
    const int half = (t >= CHUNK) ? 1 : 0;
    const int nl = t - half * CHUNK;           // n-lane 0..111 (for t < 224)
    const int n = c * CHUNK + nl;
    const bool active = (t < 2 * CHUNK) && (n < NN);

    float i0 = 0.f, i1 = 0.f, i2 = 0.f, a0 = 0.f, a1 = 0.f, a2 = 0.f, shift = 0.f;
    if (active) {
        i0 = base_in[n * 3]; i1 = base_in[n * 3 + 1]; i2 = base_in[n * 3 + 2];
        float x[DD];
#pragma unroll
        for (int j = 0; j < DD; j++)
            x[j] = fmaf(i0, wsm[j], fmaf(i1, wsm[5 + j], fmaf(i2, wsm[10 + j], wsm[15 + j])));
        float q[DD];
#pragma unroll
        for (int j = 0; j < DD; j++) {
            float qq = wsm[45 + j];
#pragma unroll
            for (int d = 0; d < DD; d++) qq = fmaf(x[d], wsm[20 + d * 5 + j], qq);
            q[j] = qq;
        }
        float wkq[DD];
#pragma unroll
        for (int d = 0; d < DD; d++) {
            float s = 0.f;
#pragma unroll
            for (int j = 0; j < DD; j++) s = fmaf(wsm[50 + d * 5 + j], q[j], s);
            wkq[d] = s;
        }
        const float qscale = 1.4426950408889634f / 2.2360679774997896f; // log2e/sqrt(5)
#pragma unroll
        for (int d = 0; d < DD; d++) {
            a0 = fmaf(wsm[0 + d], wkq[d], a0);
            a1 = fmaf(wsm[5 + d], wkq[d], a1);
            a2 = fmaf(wsm[10 + d], wkq[d], a2);
        }
        a0 *= qscale; a1 *= qscale; a2 *= qscale;
        // shift >= max_m alpha . in[m] (Cauchy-Schwarz); identical for both halves.
        shift = sqrtf(fmaf(a0, a0, fmaf(a1, a1, a2 * a2))) * sqrtf(maxn2);

        unsigned ah0 = f2h2(a0, a0), ah1 = f2h2(a1, a1), ah2 = f2h2(a2, a2);
        unsigned nsh = f2h2(-shift, -shift);

        const uint4* G0 = (const uint4*)H0;    // 250 groups of 8 points
        const uint4* G1 = (const uint4*)H1;
        const uint4* G2 = (const uint4*)H2;

        const int pb = half ? 130 : 0;
        const int ng = half ? 12 : 13;         // 13 groups x 10 / 12 x 10

        float zf = 0.f;
        for (int o = 0; o < ng; o++) {
            unsigned acc0 = 0, acc1 = 0, acc2 = 0, acc3 = 0;   // f16x2 partials
#pragma unroll
            for (int i = 0; i < 10; i++) {
                int p = pb + o * 10 + i;
                uint4 x0 = G0[p], x1 = G1[p], x2 = G2[p];
                unsigned v;
                v = hfma2_(ah2, x2.x, nsh);
                v = hfma2_(ah1, x1.x, v);
                v = hfma2_(ah0, x0.x, v);
                acc0 = hadd2_(acc0, ex2h2(v));
                v = hfma2_(ah2, x2.y, nsh);
                v = hfma2_(ah1, x1.y, v);
                v = hfma2_(ah0, x0.y, v);
                acc1 = hadd2_(acc1, ex2h2(v));
                v = hfma2_(ah2, x2.z, nsh);
                v = hfma2_(ah1, x1.z, v);
                v = hfma2_(ah0, x0.z, v);
                acc2 = hadd2_(acc2, ex2h2(v));
                v = hfma2_(ah2, x2.w, nsh);
                v = hfma2_(ah1, x1.w, v);
                v = hfma2_(ah0, x0.w, v);
                acc3 = hadd2_(acc3, ex2h2(v));
            }
            zf += (h2sum(acc0) + h2sum(acc1)) + (h2sum(acc2) + h2sum(acc3));
        }
        partial[t] = zf;
    }
    __syncthreads();

    if (active && half == 0) {
        float zsum = partial[t] + partial[t + CHUNK];
        float vn = fmaf(a0, i0, fmaf(a1, i1, a2 * i2)) - shift;   // fp32-exact numerator
        g_diag[b * NN + n] = ex2(vn) / zsum;
    }

    // ---- arrival: last block of batch b runs selection ----
    __threadfence();
    __syncthreads();
    if (t == 0) {
        unsigned old = atomicAdd(&g_cnt[b], 1u);
        s_last = ((old % NCHUNK) == NCHUNK - 1) ? 1 : 0;
    }
    __syncthreads();
    if (!s_last) return;
    __threadfence();

    // ================= selection (one block per batch) ====================
    const float* db = g_diag + b * NN;

    // group sums + argmax (first-max tie-break == jnp.argmax)
    {
        float bv = -1e30f; int gi = 1 << 30;
        for (int g = t; g < NN / GRP; g += TPB) {
            const float* d5 = db + g * GRP;
            float s = d5[0] + d5[1] + d5[2] + d5[3] + d5[4];
            if (s > bv) { bv = s; gi = g; }
        }
#pragma unroll
        for (int o = 16; o; o >>= 1) {
            float ov = __shfl_xor_sync(0xffffffffu, bv, o);
            int   oi = __shfl_xor_sync(0xffffffffu, gi, o);
            if (ov > bv || (ov == bv && oi < gi)) { bv = ov; gi = oi; }
        }
        if ((t & 31) == 0) { redf[t >> 5] = bv; redi[t >> 5] = gi; }
        __syncthreads();
        if (t == 0) {
            float v = redf[0]; int gi2 = redi[0];
#pragma unroll
            for (int i = 1; i < 8; i++)
                if (redf[i] > v || (redf[i] == v && redi[i] < gi2)) { v = redf[i]; gi2 = redi[i]; }
            const float* gp = base_in + gi2 * GRP * 3;
            float cx = 0.f, cy = 0.f, cz = 0.f;
#pragma unroll
            for (int p = 0; p < GRP; p++) {
                cx += gp[p * 3 + 0]; cy += gp[p * 3 + 1]; cz += gp[p * 3 + 2];
            }
            cen[0] = cx * 0.2f; cen[1] = cy * 0.2f; cen[2] = cz * 0.2f;
        }
        __syncthreads();
    }

    u64* key  = (u64*)sbuf;
    int* hist = (int*)(sbuf + 16000);
    u64* cand = (u64*)(sbuf + 18048);

    // distances -> keys, min/max reduction
    {
        float cx = cen[0], cy = cen[1], cz = cen[2];
        float dmin = 1e30f, dmax = 0.0f;
        for (int m = t; m < NN; m += TPB) {
            const float* p = base_in + m * 3;
            float dx = p[0] - cx, dy = p[1] - cy, dz = p[2] - cz;
            float d = sqrtf(fmaf(dx, dx, fmaf(dy, dy, dz * dz)));
            key[m] = (((u64)__float_as_uint(d)) << 11) | (unsigned)m;
            dmin = fminf(dmin, d); dmax = fmaxf(dmax, d);
        }
#pragma unroll
        for (int o = 16; o; o >>= 1) {
            dmin = fminf(dmin, __shfl_xor_sync(0xffffffffu, dmin, o));
            dmax = fmaxf(dmax, __shfl_xor_sync(0xffffffffu, dmax, o));
        }
        if ((t & 31) == 0) { redf[t >> 5] = dmin; redf2[t >> 5] = dmax; }
        __syncthreads();
        if (t == 0) {
            float mn = redf[0], mx = redf2[0];
#pragma unroll
            for (int i = 1; i < 8; i++) { mn = fminf(mn, redf[i]); mx = fmaxf(mx, redf2[i]); }
            s_dmin = mn; s_dmax = mx;
        }
    }

    for (int i = t; i < 512; i += TPB) hist[i] = 0;
    if (t == 0) s_ncand = 0;
    __syncthreads();
    float dmin = s_dmin, dmax = s_dmax;
    float scale = (dmax > dmin) ? 511.0f / (dmax - dmin) : 0.0f;
    for (int m = t; m < NN; m += TPB) {
        float d = __uint_as_float((unsigned)(key[m] >> 11));
        int bin = min((int)((d - dmin) * scale), 511);
        atomicAdd(&hist[bin], 1);
    }
    __syncthreads();
    if (t == 0) {
        int cum = 0, bs = 511;
        for (int i = 0; i < 512; i++) { cum += hist[i]; if (cum >= TOPK) { bs = i; break; } }
        s_bstar = bs;
    }
    __syncthreads();
    int bs = s_bstar;

    // compact candidates (bin <= bs): binning is value-monotone, so candidate
    // rank among candidates == global rank.
    for (int m = t; m < NN; m += TPB) {
        u64 kk = key[m];
        float d = __uint_as_float((unsigned)(kk >> 11));
        int bin = min((int)((d - dmin) * scale), 511);
        if (bin <= bs) { int pos = atomicAdd(&s_ncand, 1); cand[pos] = kk; }
    }
    __syncthreads();
    int nc = s_ncand;

    // exact stable rank among candidates (== jax.lax.top_k order); emit top-110
    for (int ci = t; ci < nc; ci += TPB) {
        u64 kn = cand[ci];
        int r = 0;
        for (int j = 0; j < nc; j++) r += (int)(cand[j] < kn);
        if (r < TOPK) {
            int m = (int)(kn & 2047u);
            const float* p = base_in + m * 3;
            float* o = out + (b * TOPK + r) * 3;
            o[0] = p[0]; o[1] = p[1]; o[2] = p[2];
        }
    }
}

// ---------------------------------------------------------------------------
extern "C" void kernel_launch(void* const* d_in, const int* in_sizes, int n_in,
                              void* d_out, int out_size) {
    const float* in_mat = (const float*)d_in[0];
    const float* Wi = (const float*)d_in[1];
    const float* bi = (const float*)d_in[2];
    const float* Wq = (const float*)d_in[3];
    const float* bq = (const float*)d_in[4];
    const float* Wk = (const float*)d_in[5];
    // bk (d_in[6]) cancels in softmax; d_in[7..10] (Wv,bv,Wo,bo) are dead.
    float* out = (float*)d_out;

    fused_kernel<<<dim3(NCHUNK, BB), TPB>>>(in_mat, Wi, bi, Wq, bq, Wk, out);
}

// round 13
// speedup vs baseline: 1.2910x; 1.0163x over previous
#include <cuda_runtime.h>

#define BB 32
#define NN 2000
#define DD 5
#define GRP 5
#define TOPK 110
#define TPB 256
#define NCHUNK 18
#define CHUNK 112          // n's per block; 2 threads per n (m-range split 1040/960)

typedef unsigned long long u64;

__device__ float g_diag[BB * NN];
__device__ unsigned int g_cnt[BB];   // monotonic; each launch adds exactly NCHUNK per batch

// ---- PTX helpers ----------------------------------------------------------
__device__ __forceinline__ float ex2(float x) {
    float y; asm("ex2.approx.ftz.f32 %0, %1;" : "=f"(y) : "f"(x)); return y;
}
__device__ __forceinline__ unsigned f2h2(float lo, float hi) {
    unsigned r; asm("cvt.rn.f16x2.f32 %0, %1, %2;" : "=r"(r) : "f"(hi), "f"(lo)); return r;
}
__device__ __forceinline__ unsigned hfma2_(unsigned a, unsigned b, unsigned c) {
    unsigned d; asm("fma.rn.f16x2 %0, %1, %2, %3;" : "=r"(d) : "r"(a), "r"(b), "r"(c)); return d;
}
__device__ __forceinline__ unsigned ex2h2(unsigned a) {
    unsigned d; asm("ex2.approx.f16x2 %0, %1;" : "=r"(d) : "r"(a)); return d;
}
__device__ __forceinline__ unsigned hadd2_(unsigned a, unsigned b) {
    unsigned d; asm("add.rn.f16x2 %0, %1, %2;" : "=r"(d) : "r"(a), "r"(b)); return d;
}
__device__ __forceinline__ float h2sum(unsigned a) {
    float lo, hi;
    asm("{.reg .b16 l,h; mov.b32 {l,h}, %2; cvt.f32.f16 %0,l; cvt.f32.f16 %1,h;}"
        : "=f"(lo), "=f"(hi) : "r"(a));
    return lo + hi;
}

// ---------------------------------------------------------------------------
// Fused kernel. grid = (18, 32), block = 256, 4 blocks/SM (regs<=64).
// score(n,m)*log2e = alpha_n . in[m] + const_n  (const cancels in softmax),
// alpha_n = (log2e/sqrt(5)) * Wi (Wk q_n)  -- 3-dim.
// TWO threads per n (m-split 1040/960). Points packed f16 in smem; inner loop
// is pure f16x2 and SOFTWARE-PIPELINED: loads for group i+1 issue before the
// compute chain of group i (double-buffered uint4 regs, compile-time indices).
//
// smem sbuf (34048 B):
//   diag phase : H0 h2[1000] @0 (4000B), H1 @4000, H2 @8000
//   select phase (overlay, last-arriving block only):
//     key u64[2000] @0, hist int[512] @16000, cand u64[2000] @18048
// ---------------------------------------------------------------------------
__global__ void __launch_bounds__(TPB, 4) fused_kernel(
    const float* __restrict__ in_mat,
    const float* __restrict__ Wi, const float* __restrict__ bi,
    const float* __restrict__ Wq, const float* __restrict__ bq,
    const float* __restrict__ Wk,
    float* __restrict__ out)
{
    __shared__ __align__(16) char sbuf[34048];
    __shared__ float wsm[75];   // 0:Wi(15) 15:bi(5) 20:Wq(25) 45:bq(5) 50:Wk(25)
    __shared__ float partial[2 * CHUNK];
    __shared__ float redf[8];
    __shared__ float redf2[8];
    __shared__ int   redi[8];
    __shared__ float cen[3];
    __shared__ int s_ncand, s_bstar, s_last;
    __shared__ float s_dmin, s_dmax;

    const int b = blockIdx.y, c = blockIdx.x, t = threadIdx.x;
    const float* base_in = in_mat + b * NN * 3;

    unsigned* H0 = (unsigned*)(sbuf);          // half2 pairs, comp 0
    unsigned* H1 = (unsigned*)(sbuf + 4000);
    unsigned* H2 = (unsigned*)(sbuf + 8000);

    // ---- stage weights ----
    if (t < 15)      wsm[t] = Wi[t];
    else if (t < 20) wsm[t] = bi[t - 15];
    else if (t < 45) wsm[t] = Wq[t - 20];
    else if (t < 50) wsm[t] = bq[t - 45];
    else if (t < 75) wsm[t] = Wk[t - 50];
    __syncthreads();

    // ---- phase 1: pack in_mat[b] as f16 SoA pairs; track max ||in||^2 ----
    float bmax = 0.0f;
    for (int pp = t; pp < NN / 2; pp += TPB) {
        const float* pe = base_in + (2 * pp) * 3;
        float e0 = pe[0], e1 = pe[1], e2 = pe[2];
        float o0 = pe[3], o1 = pe[4], o2 = pe[5];
        H0[pp] = f2h2(e0, o0);
        H1[pp] = f2h2(e1, o1);
        H2[pp] = f2h2(e2, o2);
        float ne = fmaf(e0, e0, fmaf(e1, e1, e2 * e2));
        float no = fmaf(o0, o0, fmaf(o1, o1, o2 * o2));
        bmax = fmaxf(bmax, fmaxf(ne, no));
    }
#pragma unroll
    for (int o = 16; o; o >>= 1) bmax = fmaxf(bmax, __shfl_xor_sync(0xffffffffu, bmax, o));
    if ((t & 31) == 0) redf[t >> 5] = bmax;
    __syncthreads();
    float maxn2 = redf[0];
#pragma unroll
    for (int i = 1; i < 8; i++) maxn2 = fmaxf(maxn2, redf[i]);

    // ---- phase 2: alpha_n; two threads per n, split m-range ----
    const int half = (t >= CHUNK) ? 1 : 0;
    const int nl = t - half * CHUNK;           // n-lane 0..111 (for t < 224)
    const int n = c * CHUNK + nl;
    const bool active = (t < 2 * CHUNK) && (n < NN);

    float i0 = 0.f, i1 = 0.f, i2 = 0.f, a0 = 0.f, a1 = 0.f, a2 = 0.f, shift = 0.f;
    if (active) {
        i0 = base_in[n * 3]; i1 = base_in[n * 3 + 1]; i2 = base_in[n * 3 + 2];
        float x[DD];
#pragma unroll
        for (int j = 0; j < DD; j++)
            x[j] = fmaf(i0, wsm[j], fmaf(i1, wsm[5 + j], fmaf(i2, wsm[10 + j], wsm[15 + j])));
        float q[DD];
#pragma unroll
        for (int j = 0; j < DD; j++) {
            float qq = wsm[45 + j];
#pragma unroll
            for (int d = 0; d < DD; d++) qq = fmaf(x[d], wsm[20 + d * 5 + j], qq);
            q[j] = qq;
        }
        float wkq[DD];
#pragma unroll
        for (int d = 0; d < DD; d++) {
            float s = 0.f;
#pragma unroll
            for (int j = 0; j < DD; j++) s = fmaf(wsm[50 + d * 5 + j], q[j], s);
            wkq[d] = s;
        }
        const float qscale = 1.4426950408889634f / 2.2360679774997896f; // log2e/sqrt(5)
#pragma unroll
        for (int d = 0; d < DD; d++) {
            a0 = fmaf(wsm[0 + d], wkq[d], a0);
            a1 = fmaf(wsm[5 + d], wkq[d], a1);
            a2 = fmaf(wsm[10 + d], wkq[d], a2);
        }
        a0 *= qscale; a1 *= qscale; a2 *= qscale;
        // shift >= max_m alpha . in[m] (Cauchy-Schwarz); identical for both halves.
        shift = sqrtf(fmaf(a0, a0, fmaf(a1, a1, a2 * a2))) * sqrtf(maxn2);

        unsigned ah0 = f2h2(a0, a0), ah1 = f2h2(a1, a1), ah2 = f2h2(a2, a2);
        unsigned nsh = f2h2(-shift, -shift);

        const uint4* G0 = (const uint4*)H0;    // 250 groups of 8 points
        const uint4* G1 = (const uint4*)H1;
        const uint4* G2 = (const uint4*)H2;

        const int pb = half ? 130 : 0;
        const int ng = half ? 12 : 13;         // 13 groups x 10 / 12 x 10

        float zf = 0.f;
        for (int o = 0; o < ng; o++) {
            const int base = pb + o * 10;
            // prime the pipeline: group 0 of this outer block
            uint4 c0 = G0[base], c1 = G1[base], c2 = G2[base];
            unsigned acc0 = 0, acc1 = 0, acc2 = 0, acc3 = 0;   // f16x2 partials
#pragma unroll
            for (int i = 0; i < 10; i++) {
                // issue next group's loads BEFORE consuming current group
                const int pn = base + ((i + 1 < 10) ? (i + 1) : 0);
                uint4 t0 = G0[pn], t1 = G1[pn], t2 = G2[pn];
                unsigned v;
                v = hfma2_(ah2, c2.x, nsh);
                v = hfma2_(ah1, c1.x, v);
                v = hfma2_(ah0, c0.x, v);
                acc0 = hadd2_(acc0, ex2h2(v));
                v = hfma2_(ah2, c2.y, nsh);
                v = hfma2_(ah1, c1.y, v);
                v = hfma2_(ah0, c0.y, v);
                acc1 = hadd2_(acc1, ex2h2(v));
                v = hfma2_(ah2, c2.z, nsh);
                v = hfma2_(ah1, c1.z, v);
                v = hfma2_(ah0, c0.z, v);
                acc2 = hadd2_(acc2, ex2h2(v));
                v = hfma2_(ah2, c2.w, nsh);
                v = hfma2_(ah1, c1.w, v);
                v = hfma2_(ah0, c0.w, v);
                acc3 = hadd2_(acc3, ex2h2(v));
                c0 = t0; c1 = t1; c2 = t2;
            }
            zf += (h2sum(acc0) + h2sum(acc1)) + (h2sum(acc2) + h2sum(acc3));
        }
        partial[t] = zf;
    }
    __syncthreads();

    if (active && half == 0) {
        float zsum = partial[t] + partial[t + CHUNK];
        float vn = fmaf(a0, i0, fmaf(a1, i1, a2 * i2)) - shift;   // fp32-exact numerator
        g_diag[b * NN + n] = ex2(vn) / zsum;
    }

    // ---- arrival: last block of batch b runs selection ----
    __threadfence();
    __syncthreads();
    if (t == 0) {
        unsigned old = atomicAdd(&g_cnt[b], 1u);
        s_last = ((old % NCHUNK) == NCHUNK - 1) ? 1 : 0;
    }
    __syncthreads();
    if (!s_last) return;
    __threadfence();

    // ================= selection (one block per batch) ====================
    const float* db = g_diag + b * NN;

    // group sums + argmax (first-max tie-break == jnp.argmax)
    {
        float bv = -1e30f; int gi = 1 << 30;
        for (int g = t; g < NN / GRP; g += TPB) {
            const float* d5 = db + g * GRP;
            float s = d5[0] + d5[1] + d5[2] + d5[3] + d5[4];
            if (s > bv) { bv = s; gi = g; }
        }
#pragma unroll
        for (int o = 16; o; o >>= 1) {
            float ov = __shfl_xor_sync(0xffffffffu, bv, o);
            int   oi = __shfl_xor_sync(0xffffffffu, gi, o);
            if (ov > bv || (ov == bv && oi < gi)) { bv = ov; gi = oi; }
        }
        if ((t & 31) == 0) { redf[t >> 5] = bv; redi[t >> 5] = gi; }
        __syncthreads();
        if (t == 0) {
            float v = redf[0]; int gi2 = redi[0];
#pragma unroll
            for (int i = 1; i < 8; i++)
                if (redf[i] > v || (redf[i] == v && redi[i] < gi2)) { v = redf[i]; gi2 = redi[i]; }
            const float* gp = base_in + gi2 * GRP * 3;
            float cx = 0.f, cy = 0.f, cz = 0.f;
#pragma unroll
            for (int p = 0; p < GRP; p++) {
                cx += gp[p * 3 + 0]; cy += gp[p * 3 + 1]; cz += gp[p * 3 + 2];
            }
            cen[0] = cx * 0.2f; cen[1] = cy * 0.2f; cen[2] = cz * 0.2f;
        }
        __syncthreads();
    }

    u64* key  = (u64*)sbuf;
    int* hist = (int*)(sbuf + 16000);
    u64* cand = (u64*)(sbuf + 18048);

    // distances -> keys, min/max reduction
    {
        float cx = cen[0], cy = cen[1], cz = cen[2];
        float dmin = 1e30f, dmax = 0.0f;
        for (int m = t; m < NN; m += TPB) {
            const float* p = base_in + m * 3;
            float dx = p[0] - cx, dy = p[1] - cy, dz = p[2] - cz;
            float d = sqrtf(fmaf(dx, dx, fmaf(dy, dy, dz * dz)));
            key[m] = (((u64)__float_as_uint(d)) << 11) | (unsigned)m;
            dmin = fminf(dmin, d); dmax = fmaxf(dmax, d);
        }
#pragma unroll
        for (int o = 16; o; o >>= 1) {
            dmin = fminf(dmin, __shfl_xor_sync(0xffffffffu, dmin, o));
            dmax = fmaxf(dmax, __shfl_xor_sync(0xffffffffu, dmax, o));
        }
        if ((t & 31) == 0) { redf[t >> 5] = dmin; redf2[t >> 5] = dmax; }
        __syncthreads();
        if (t == 0) {
            float mn = redf[0], mx = redf2[0];
#pragma unroll
            for (int i = 1; i < 8; i++) { mn = fminf(mn, redf[i]); mx = fmaxf(mx, redf2[i]); }
            s_dmin = mn; s_dmax = mx;
        }
    }

    for (int i = t; i < 512; i += TPB) hist[i] = 0;
    if (t == 0) s_ncand = 0;
    __syncthreads();
    float dmin = s_dmin, dmax = s_dmax;
    float scale = (dmax > dmin) ? 511.0f / (dmax - dmin) : 0.0f;
    for (int m = t; m < NN; m += TPB) {
        float d = __uint_as_float((unsigned)(key[m] >> 11));
        int bin = min((int)((d - dmin) * scale), 511);
        atomicAdd(&hist[bin], 1);
    }
    __syncthreads();
    if (t == 0) {
        int cum = 0, bs = 511;
        for (int i = 0; i < 512; i++) { cum += hist[i]; if (cum >= TOPK) { bs = i; break; } }
        s_bstar = bs;
    }
    __syncthreads();
    int bs = s_bstar;

    // compact candidates (bin <= bs): binning is value-monotone, so candidate
    // rank among candidates == global rank.
    for (int m = t; m < NN; m += TPB) {
        u64 kk = key[m];
        float d = __uint_as_float((unsigned)(kk >> 11));
        int bin = min((int)((d - dmin) * scale), 511);
        if (bin <= bs) { int pos = atomicAdd(&s_ncand, 1); cand[pos] = kk; }
    }
    __syncthreads();
    int nc = s_ncand;

    // exact stable rank among candidates (== jax.lax.top_k order); emit top-110
    for (int ci = t; ci < nc; ci += TPB) {
        u64 kn = cand[ci];
        int r = 0;
        for (int j = 0; j < nc; j++) r += (int)(cand[j] < kn);
        if (r < TOPK) {
            int m = (int)(kn & 2047u);
            const float* p = base_in + m * 3;
            float* o = out + (b * TOPK + r) * 3;
            o[0] = p[0]; o[1] = p[1]; o[2] = p[2];
        }
    }
}

// ---------------------------------------------------------------------------
extern "C" void kernel_launch(void* const* d_in, const int* in_sizes, int n_in,
                              void* d_out, int out_size) {
    const float* in_mat = (const float*)d_in[0];
    const float* Wi = (const float*)d_in[1];
    const float* bi = (const float*)d_in[2];
    const float* Wq = (const float*)d_in[3];
    const float* bq = (const float*)d_in[4];
    const float* Wk = (const float*)d_in[5];
    // bk (d_in[6]) cancels in softmax; d_in[7..10] (Wv,bv,Wo,bo) are dead.
    float* out = (float*)d_out;

    fused_kernel<<<dim3(NCHUNK, BB), TPB>>>(in_mat, Wi, bi, Wq, bq, Wk, out);
}